// round 1
// baseline (speedup 1.0000x reference)
#include <cuda_runtime.h>
#include <cstdint>

// GraphPool: degree-bucketed max pool over self + neighbor features.
// atoms: [200000, 128] f32. For degree-d rows: out = max(self, max_j atoms[adj[j]]).
//
// Strategy: 1 warp per output row; lane l owns float4 l (128 floats = 32 float4).
// Neighbor indices are loaded in parallel (lane < d) and broadcast via shfl.

#define MAX_DEG 10
#define N_FEAT4 32                 // 128 floats = 32 float4 per row
#define N_ATOMS 200000

// Cumulative row boundaries: starts of each degree bucket + total.
__device__ __constant__ const int kBounds[12] = {
    0, 10000, 30000, 70000, 120000, 160000, 180000, 190000, 195000, 198000, 199500, 200000
};

struct AdjPtrs {
    const int* p[MAX_DEG + 1];     // p[d] valid for d in 1..10
};

__global__ __launch_bounds__(256, 8)
void graph_pool_kernel(const float4* __restrict__ atoms4,
                       AdjPtrs adj,
                       float4* __restrict__ out4)
{
    const int warps_per_block = blockDim.x >> 5;
    const int row  = blockIdx.x * warps_per_block + (threadIdx.x >> 5);
    const int lane = threadIdx.x & 31;
    if (row >= N_ATOMS) return;

    // Warp-uniform degree-bucket lookup (hardcoded boundaries).
    int d, local;
    if      (row < 10000)  { d = 0;  local = row; }
    else if (row < 30000)  { d = 1;  local = row - 10000; }
    else if (row < 70000)  { d = 2;  local = row - 30000; }
    else if (row < 120000) { d = 3;  local = row - 70000; }
    else if (row < 160000) { d = 4;  local = row - 120000; }
    else if (row < 180000) { d = 5;  local = row - 160000; }
    else if (row < 190000) { d = 6;  local = row - 180000; }
    else if (row < 195000) { d = 7;  local = row - 190000; }
    else if (row < 198000) { d = 8;  local = row - 195000; }
    else if (row < 199500) { d = 9;  local = row - 198000; }
    else                   { d = 10; local = row - 199500; }

    // Self row.
    float4 v = __ldg(atoms4 + (size_t)row * N_FEAT4 + lane);

    if (d > 0) {
        // Parallel index load: lane j (< d) fetches neighbor j, broadcast later.
        const int* arow = adj.p[d] + (size_t)local * d;
        int my_idx = (lane < d) ? __ldg(arow + lane) : 0;

        #pragma unroll 2
        for (int j = 0; j < d; ++j) {
            int n = __shfl_sync(0xffffffffu, my_idx, j);
            float4 g = __ldg(atoms4 + (size_t)n * N_FEAT4 + lane);
            v.x = fmaxf(v.x, g.x);
            v.y = fmaxf(v.y, g.y);
            v.z = fmaxf(v.z, g.z);
            v.w = fmaxf(v.w, g.w);
        }
    }

    out4[(size_t)row * N_FEAT4 + lane] = v;
}

extern "C" void kernel_launch(void* const* d_in, const int* in_sizes, int n_in,
                              void* d_out, int out_size)
{
    const float4* atoms4 = (const float4*)d_in[0];
    // d_in[1] = deg_slice (unused; STARTS/COUNTS are compile-time constants)
    AdjPtrs adj;
    adj.p[0] = nullptr;
    for (int d = 1; d <= MAX_DEG; ++d)
        adj.p[d] = (const int*)d_in[1 + d];

    float4* out4 = (float4*)d_out;

    const int threads = 256;                     // 8 warps = 8 rows per block
    const int warps_per_block = threads / 32;
    const int blocks = (N_ATOMS + warps_per_block - 1) / warps_per_block;
    graph_pool_kernel<<<blocks, threads>>>(atoms4, adj, out4);
}

// round 2
// speedup vs baseline: 1.3996x; 1.3996x over previous
#include <cuda_runtime.h>
#include <cstdint>

// GraphPool: degree-bucketed max pool over self + neighbor features.
// atoms: [200000, 128] f32. For degree-d rows: out = max(self, max_j atoms[adj[j]]).
//
// R2: warp-per-row; switch(d) -> fully unrolled templated body so all gather
// LDG.128s are front-batched (MLP=d+1). Output stored with __stcs (evict-first)
// so the out stream doesn't evict atoms from L2; gathers use __ldcg.

#define MAX_DEG 10
#define N_FEAT4 32                 // 128 floats = 32 float4 per row
#define N_ATOMS 200000

struct AdjPtrs {
    const int* p[MAX_DEG + 1];     // p[d] valid for d in 1..10
};

__device__ __forceinline__ float4 fmax4(float4 a, float4 b) {
    a.x = fmaxf(a.x, b.x);
    a.y = fmaxf(a.y, b.y);
    a.z = fmaxf(a.z, b.z);
    a.w = fmaxf(a.w, b.w);
    return a;
}

template <int D>
__device__ __forceinline__ void pool_row(const float4* __restrict__ atoms4,
                                         const int* __restrict__ arow,
                                         int row, int lane,
                                         float4* __restrict__ out4)
{
    // Self row (default caching: self rows are also gather targets -> keep in L2).
    float4 v = __ldg(atoms4 + (size_t)row * N_FEAT4 + lane);

    // Parallel index load: lane j (< D) fetches neighbor j, broadcast via shfl.
    int my_idx = (lane < D) ? __ldg(arow + lane) : 0;

    float4 gv[D];
    #pragma unroll
    for (int j = 0; j < D; ++j) {
        int n = __shfl_sync(0xffffffffu, my_idx, j);
        gv[j] = __ldcg(atoms4 + (size_t)n * N_FEAT4 + lane);
    }
    #pragma unroll
    for (int j = 0; j < D; ++j)
        v = fmax4(v, gv[j]);

    // Streaming store: don't let the output stream evict atoms from L2.
    __stcs(out4 + (size_t)row * N_FEAT4 + lane, v);
}

__global__ __launch_bounds__(256)
void graph_pool_kernel(const float4* __restrict__ atoms4,
                       AdjPtrs adj,
                       float4* __restrict__ out4)
{
    const int warps_per_block = blockDim.x >> 5;
    const int row  = blockIdx.x * warps_per_block + (threadIdx.x >> 5);
    const int lane = threadIdx.x & 31;
    if (row >= N_ATOMS) return;

    // Warp-uniform degree-bucket lookup (1 warp = 1 row, so d is uniform).
    int d, local;
    if      (row < 10000)  { d = 0;  local = row; }
    else if (row < 30000)  { d = 1;  local = row - 10000; }
    else if (row < 70000)  { d = 2;  local = row - 30000; }
    else if (row < 120000) { d = 3;  local = row - 70000; }
    else if (row < 160000) { d = 4;  local = row - 120000; }
    else if (row < 180000) { d = 5;  local = row - 160000; }
    else if (row < 190000) { d = 6;  local = row - 180000; }
    else if (row < 195000) { d = 7;  local = row - 190000; }
    else if (row < 198000) { d = 8;  local = row - 195000; }
    else if (row < 199500) { d = 9;  local = row - 198000; }
    else                   { d = 10; local = row - 199500; }

    const int* arow = (d > 0) ? (adj.p[d] + (size_t)local * d) : nullptr;

    switch (d) {
    case 0: {
        float4 v = __ldg(atoms4 + (size_t)row * N_FEAT4 + lane);
        __stcs(out4 + (size_t)row * N_FEAT4 + lane, v);
        break;
    }
    case 1:  pool_row<1>(atoms4, arow, row, lane, out4); break;
    case 2:  pool_row<2>(atoms4, arow, row, lane, out4); break;
    case 3:  pool_row<3>(atoms4, arow, row, lane, out4); break;
    case 4:  pool_row<4>(atoms4, arow, row, lane, out4); break;
    case 5:  pool_row<5>(atoms4, arow, row, lane, out4); break;
    case 6:  pool_row<6>(atoms4, arow, row, lane, out4); break;
    case 7:  pool_row<7>(atoms4, arow, row, lane, out4); break;
    case 8:  pool_row<8>(atoms4, arow, row, lane, out4); break;
    case 9:  pool_row<9>(atoms4, arow, row, lane, out4); break;
    default: pool_row<10>(atoms4, arow, row, lane, out4); break;
    }
}

extern "C" void kernel_launch(void* const* d_in, const int* in_sizes, int n_in,
                              void* d_out, int out_size)
{
    const float4* atoms4 = (const float4*)d_in[0];
    // d_in[1] = deg_slice (unused; STARTS/COUNTS are compile-time constants)
    AdjPtrs adj;
    adj.p[0] = nullptr;
    for (int d = 1; d <= MAX_DEG; ++d)
        adj.p[d] = (const int*)d_in[1 + d];

    float4* out4 = (float4*)d_out;

    const int threads = 256;                     // 8 warps = 8 rows per block
    const int warps_per_block = threads / 32;
    const int blocks = (N_ATOMS + warps_per_block - 1) / warps_per_block;
    graph_pool_kernel<<<blocks, threads>>>(atoms4, adj, out4);
}

// round 4
// speedup vs baseline: 1.8762x; 1.3405x over previous
#include <cuda_runtime.h>
#include <cstdint>

// GraphPool: degree-bucketed max pool over self + neighbor features.
// atoms: [200000, 128] f32. For degree-d rows: out = max(self, max_j atoms[adj[j]]).
//
// R4: 2 rows per warp; lanes 0-15 own row0, lanes 16-31 own row1, 32B (float8)
// per lane. All atoms reads are 256-bit ld.global.nc.L2::evict_last.v8.b32
// (sm_103 requires v8 for evict_last) -> half the load instructions of R2 and
// atoms pinned in L2 against the evict-first (__stcs) output stream.

#define MAX_DEG 10
#define N_FEAT 128
#define N_ATOMS 200000
#define N_PAIRS (N_ATOMS / 2)

struct AdjPtrs {
    const int* p[MAX_DEG + 1];     // p[d] valid for d in 1..10
};

// 256-bit read-only load with L2 evict-last priority. p must be 32B-aligned.
__device__ __forceinline__ void ldg256_el(const float* __restrict__ p, float v[8]) {
    unsigned r0, r1, r2, r3, r4, r5, r6, r7;
    asm("ld.global.nc.L2::evict_last.v8.b32 {%0,%1,%2,%3,%4,%5,%6,%7}, [%8];"
        : "=r"(r0), "=r"(r1), "=r"(r2), "=r"(r3),
          "=r"(r4), "=r"(r5), "=r"(r6), "=r"(r7)
        : "l"(p));
    v[0] = __uint_as_float(r0); v[1] = __uint_as_float(r1);
    v[2] = __uint_as_float(r2); v[3] = __uint_as_float(r3);
    v[4] = __uint_as_float(r4); v[5] = __uint_as_float(r5);
    v[6] = __uint_as_float(r6); v[7] = __uint_as_float(r7);
}

__device__ __forceinline__ void store_row8(float* __restrict__ p, const float v[8]) {
    __stcs((float4*)p,       make_float4(v[0], v[1], v[2], v[3]));
    __stcs((float4*)(p + 4), make_float4(v[4], v[5], v[6], v[7]));
}

template <int D>
__device__ __forceinline__ void pool_pair(const float* __restrict__ atoms,
                                          const int* __restrict__ arow0,
                                          int row0, int lane,
                                          float* __restrict__ out)
{
    const int half = lane >> 4;          // 0 -> row0, 1 -> row1
    const int sub  = lane & 15;          // which 32B chunk of the row
    const int row  = row0 + half;
    const size_t foff = (size_t)sub * 8;

    // Self row (both rows of the pair in flight, 1024B total).
    float v[8];
    ldg256_el(atoms + (size_t)row * N_FEAT + foff, v);

    // Index loads: lane (half,k) owns neighbor k of its row (k = lane & 15).
    int myidx = (sub < D) ? __ldg(arow0 + half * D + sub) : 0;

    // Gather waves: batch all D for D<=5, else split to bound registers.
    constexpr int CH = (D <= 5) ? D : (D + 1) / 2;

    #pragma unroll
    for (int base = 0; base < D; base += CH) {
        float g[CH][8];
        #pragma unroll
        for (int j = 0; j < CH; ++j) {
            if (base + j < D) {
                // Broadcast neighbor index from the lane of MY half that owns it.
                int n = __shfl_sync(0xffffffffu, myidx, (half << 4) + base + j);
                ldg256_el(atoms + (size_t)n * N_FEAT + foff, g[j]);
            }
        }
        #pragma unroll
        for (int j = 0; j < CH; ++j) {
            if (base + j < D) {
                #pragma unroll
                for (int e = 0; e < 8; ++e)
                    v[e] = fmaxf(v[e], g[j][e]);
            }
        }
    }

    store_row8(out + (size_t)row * N_FEAT + foff, v);
}

__global__ __launch_bounds__(128)
void graph_pool_kernel(const float* __restrict__ atoms,
                       AdjPtrs adj,
                       float* __restrict__ out)
{
    const int warps_per_block = blockDim.x >> 5;
    const int pair = blockIdx.x * warps_per_block + (threadIdx.x >> 5);
    const int lane = threadIdx.x & 31;
    if (pair >= N_PAIRS) return;

    const int row0 = pair * 2;

    // Bucket lookup (all bucket starts even -> row0, row0+1 share a bucket).
    int d, local;
    if      (row0 < 10000)  { d = 0;  local = row0; }
    else if (row0 < 30000)  { d = 1;  local = row0 - 10000; }
    else if (row0 < 70000)  { d = 2;  local = row0 - 30000; }
    else if (row0 < 120000) { d = 3;  local = row0 - 70000; }
    else if (row0 < 160000) { d = 4;  local = row0 - 120000; }
    else if (row0 < 180000) { d = 5;  local = row0 - 160000; }
    else if (row0 < 190000) { d = 6;  local = row0 - 180000; }
    else if (row0 < 195000) { d = 7;  local = row0 - 190000; }
    else if (row0 < 198000) { d = 8;  local = row0 - 195000; }
    else if (row0 < 199500) { d = 9;  local = row0 - 198000; }
    else                    { d = 10; local = row0 - 199500; }

    const int* arow0 = (d > 0) ? (adj.p[d] + (size_t)local * d) : nullptr;

    switch (d) {
    case 0: {
        const int half = lane >> 4;
        const int sub  = lane & 15;
        const int row  = row0 + half;
        float v[8];
        ldg256_el(atoms + (size_t)row * N_FEAT + (size_t)sub * 8, v);
        store_row8(out + (size_t)row * N_FEAT + (size_t)sub * 8, v);
        break;
    }
    case 1:  pool_pair<1>(atoms, arow0, row0, lane, out); break;
    case 2:  pool_pair<2>(atoms, arow0, row0, lane, out); break;
    case 3:  pool_pair<3>(atoms, arow0, row0, lane, out); break;
    case 4:  pool_pair<4>(atoms, arow0, row0, lane, out); break;
    case 5:  pool_pair<5>(atoms, arow0, row0, lane, out); break;
    case 6:  pool_pair<6>(atoms, arow0, row0, lane, out); break;
    case 7:  pool_pair<7>(atoms, arow0, row0, lane, out); break;
    case 8:  pool_pair<8>(atoms, arow0, row0, lane, out); break;
    case 9:  pool_pair<9>(atoms, arow0, row0, lane, out); break;
    default: pool_pair<10>(atoms, arow0, row0, lane, out); break;
    }
}

extern "C" void kernel_launch(void* const* d_in, const int* in_sizes, int n_in,
                              void* d_out, int out_size)
{
    const float* atoms = (const float*)d_in[0];
    // d_in[1] = deg_slice (unused; STARTS/COUNTS are compile-time constants)
    AdjPtrs adj;
    adj.p[0] = nullptr;
    for (int d = 1; d <= MAX_DEG; ++d)
        adj.p[d] = (const int*)d_in[1 + d];

    float* out = (float*)d_out;

    const int threads = 128;                     // 4 warps = 4 pairs per block
    const int pairs_per_block = threads / 32;
    const int blocks = (N_PAIRS + pairs_per_block - 1) / pairs_per_block;
    graph_pool_kernel<<<blocks, threads>>>(atoms, adj, out);
}

// round 5
// speedup vs baseline: 1.9080x; 1.0169x over previous
#include <cuda_runtime.h>
#include <cstdint>

// GraphPool: degree-bucketed max pool over self + neighbor features.
// atoms: [200000, 128] f32. For degree-d rows: out = max(self, max_j atoms[adj[j]]).
//
// R5: 4 rows (= 2 pairs) per warp. All bucket starts are divisible by 4, so a
// quad never straddles a bucket. Both pairs' index loads + self loads issue
// up front, then both pairs' gather waves issue before any consumption ->
// 2x gather-epoch bytes in flight per warp vs R4. Lanes 0-15 own the even row
// of each pair, lanes 16-31 the odd row; 32B (float8) per lane via
// ld.global.nc.L2::evict_last.v8.b32; output via __stcs (evict-first).

#define MAX_DEG 10
#define N_FEAT 128
#define N_ATOMS 200000
#define N_QUADS (N_ATOMS / 4)

struct AdjPtrs {
    const int* p[MAX_DEG + 1];     // p[d] valid for d in 1..10
};

// 256-bit read-only load with L2 evict-last priority. p must be 32B-aligned.
__device__ __forceinline__ void ldg256_el(const float* __restrict__ p, float v[8]) {
    unsigned r0, r1, r2, r3, r4, r5, r6, r7;
    asm("ld.global.nc.L2::evict_last.v8.b32 {%0,%1,%2,%3,%4,%5,%6,%7}, [%8];"
        : "=r"(r0), "=r"(r1), "=r"(r2), "=r"(r3),
          "=r"(r4), "=r"(r5), "=r"(r6), "=r"(r7)
        : "l"(p));
    v[0] = __uint_as_float(r0); v[1] = __uint_as_float(r1);
    v[2] = __uint_as_float(r2); v[3] = __uint_as_float(r3);
    v[4] = __uint_as_float(r4); v[5] = __uint_as_float(r5);
    v[6] = __uint_as_float(r6); v[7] = __uint_as_float(r7);
}

__device__ __forceinline__ void store_row8(float* __restrict__ p, const float v[8]) {
    __stcs((float4*)p,       make_float4(v[0], v[1], v[2], v[3]));
    __stcs((float4*)(p + 4), make_float4(v[4], v[5], v[6], v[7]));
}

template <int D>
__device__ __forceinline__ void pool_quad(const float* __restrict__ atoms,
                                          const int* __restrict__ arowA,
                                          int row0, int lane,
                                          float* __restrict__ out)
{
    const int half = lane >> 4;          // 0 -> even row of pair, 1 -> odd row
    const int sub  = lane & 15;          // which 32B chunk of the row
    const int rowA = row0 + half;        // pair A: rows row0, row0+1
    const int rowB = row0 + 2 + half;    // pair B: rows row0+2, row0+3
    const size_t foff = (size_t)sub * 8;

    // Index loads for BOTH pairs first (lane (half, sub<D) owns neighbor sub).
    int ia = (sub < D) ? __ldg(arowA + half * D + sub) : 0;
    int ib = (sub < D) ? __ldg(arowA + 2 * D + half * D + sub) : 0;

    // Self rows for both pairs (2 KB in flight with the index loads).
    float va[8], vb[8];
    ldg256_el(atoms + (size_t)rowA * N_FEAT + foff, va);
    ldg256_el(atoms + (size_t)rowB * N_FEAT + foff, vb);

    // Gather waves: both pairs' loads issue back-to-back before consumption.
    constexpr int CH = (D <= 3) ? D : 3;

    #pragma unroll
    for (int base = 0; base < D; base += CH) {
        float ga[CH][8], gb[CH][8];
        #pragma unroll
        for (int j = 0; j < CH; ++j) {
            if (base + j < D) {
                int na = __shfl_sync(0xffffffffu, ia, (half << 4) + base + j);
                ldg256_el(atoms + (size_t)na * N_FEAT + foff, ga[j]);
                int nb = __shfl_sync(0xffffffffu, ib, (half << 4) + base + j);
                ldg256_el(atoms + (size_t)nb * N_FEAT + foff, gb[j]);
            }
        }
        #pragma unroll
        for (int j = 0; j < CH; ++j) {
            if (base + j < D) {
                #pragma unroll
                for (int e = 0; e < 8; ++e) {
                    va[e] = fmaxf(va[e], ga[j][e]);
                    vb[e] = fmaxf(vb[e], gb[j][e]);
                }
            }
        }
    }

    store_row8(out + (size_t)rowA * N_FEAT + foff, va);
    store_row8(out + (size_t)rowB * N_FEAT + foff, vb);
}

__global__ __launch_bounds__(128, 6)
void graph_pool_kernel(const float* __restrict__ atoms,
                       AdjPtrs adj,
                       float* __restrict__ out)
{
    const int warps_per_block = blockDim.x >> 5;
    const int quad = blockIdx.x * warps_per_block + (threadIdx.x >> 5);
    const int lane = threadIdx.x & 31;
    if (quad >= N_QUADS) return;

    const int row0 = quad * 4;

    // Bucket lookup (all bucket starts divisible by 4 -> quad shares a bucket).
    int d, local;
    if      (row0 < 10000)  { d = 0;  local = row0; }
    else if (row0 < 30000)  { d = 1;  local = row0 - 10000; }
    else if (row0 < 70000)  { d = 2;  local = row0 - 30000; }
    else if (row0 < 120000) { d = 3;  local = row0 - 70000; }
    else if (row0 < 160000) { d = 4;  local = row0 - 120000; }
    else if (row0 < 180000) { d = 5;  local = row0 - 160000; }
    else if (row0 < 190000) { d = 6;  local = row0 - 180000; }
    else if (row0 < 195000) { d = 7;  local = row0 - 190000; }
    else if (row0 < 198000) { d = 8;  local = row0 - 195000; }
    else if (row0 < 199500) { d = 9;  local = row0 - 198000; }
    else                    { d = 10; local = row0 - 199500; }

    const int* arowA = (d > 0) ? (adj.p[d] + (size_t)local * d) : nullptr;

    switch (d) {
    case 0: {
        const int half = lane >> 4;
        const int sub  = lane & 15;
        const size_t foff = (size_t)sub * 8;
        const int rowA = row0 + half;
        const int rowB = row0 + 2 + half;
        float va[8], vb[8];
        ldg256_el(atoms + (size_t)rowA * N_FEAT + foff, va);
        ldg256_el(atoms + (size_t)rowB * N_FEAT + foff, vb);
        store_row8(out + (size_t)rowA * N_FEAT + foff, va);
        store_row8(out + (size_t)rowB * N_FEAT + foff, vb);
        break;
    }
    case 1:  pool_quad<1>(atoms, arowA, row0, lane, out); break;
    case 2:  pool_quad<2>(atoms, arowA, row0, lane, out); break;
    case 3:  pool_quad<3>(atoms, arowA, row0, lane, out); break;
    case 4:  pool_quad<4>(atoms, arowA, row0, lane, out); break;
    case 5:  pool_quad<5>(atoms, arowA, row0, lane, out); break;
    case 6:  pool_quad<6>(atoms, arowA, row0, lane, out); break;
    case 7:  pool_quad<7>(atoms, arowA, row0, lane, out); break;
    case 8:  pool_quad<8>(atoms, arowA, row0, lane, out); break;
    case 9:  pool_quad<9>(atoms, arowA, row0, lane, out); break;
    default: pool_quad<10>(atoms, arowA, row0, lane, out); break;
    }
}

extern "C" void kernel_launch(void* const* d_in, const int* in_sizes, int n_in,
                              void* d_out, int out_size)
{
    const float* atoms = (const float*)d_in[0];
    // d_in[1] = deg_slice (unused; STARTS/COUNTS are compile-time constants)
    AdjPtrs adj;
    adj.p[0] = nullptr;
    for (int d = 1; d <= MAX_DEG; ++d)
        adj.p[d] = (const int*)d_in[1 + d];

    float* out = (float*)d_out;

    const int threads = 128;                     // 4 warps = 4 quads per block
    const int quads_per_block = threads / 32;
    const int blocks = (N_QUADS + quads_per_block - 1) / quads_per_block;
    graph_pool_kernel<<<blocks, threads>>>(atoms, adj, out);
}